// round 11
// baseline (speedup 1.0000x reference)
#include <cuda_runtime.h>
#include <cuda_bf16.h>
#include <cstdint>

#define B_ 32
#define D_ 128
#define T_ 2250
#define Q_ 32
#define K_ 1024
#define N_ (B_*T_)          // 72000
#define NBLK 563            // ceil(N/128)
#define WIN 0.02f           // candidate window = 2 * approx-error bound
#define NCAND 5

#define EPITCH 392          // padded bf16 per row (784 B; 784 % 128 == 16)
#define ROWB 784

// Residual [N][D], code norms [Q][K], padded split-bf16 codebooks [Q*K][392]
__device__ __align__(16) float g_resid[(size_t)N_ * D_];
__device__ __align__(16) float g_cnorm[Q_ * K_];
__device__ __align__(16) __nv_bfloat16 g_e2[(size_t)Q_ * K_ * EPITCH];

// ---------------------------------------------------------------------------
__global__ void transpose_kernel(const float* __restrict__ in)
{
    __shared__ float tile[32][33];
    const int b  = blockIdx.z;
    const int t0 = blockIdx.x * 32;
    const int d0 = blockIdx.y * 32;
    const int tx = threadIdx.x;
    const int ty = threadIdx.y;

    #pragma unroll
    for (int k = 0; k < 4; k++) {
        int d = d0 + ty + k * 8;
        int t = t0 + tx;
        float v = 0.0f;
        if (t < T_) v = in[((size_t)b * D_ + d) * T_ + t];
        tile[ty + k * 8][tx] = v;
    }
    __syncthreads();
    #pragma unroll
    for (int k = 0; k < 4; k++) {
        int t = t0 + ty + k * 8;
        int d = d0 + tx;
        if (t < T_) g_resid[((size_t)b * T_ + t) * D_ + d] = tile[tx][ty + k * 8];
    }
}

// ---------------------------------------------------------------------------
__global__ void cnorm_kernel(const float* __restrict__ embed)
{
    const int wid  = threadIdx.x >> 5;
    const int lane = threadIdx.x & 31;
    const int code = blockIdx.x * 8 + wid;
    float s = 0.0f;
    #pragma unroll
    for (int j = 0; j < 4; j++) {
        float v = embed[(size_t)code * D_ + lane + 32 * j];
        s = fmaf(v, v, s);
    }
    #pragma unroll
    for (int d = 16; d; d >>= 1) s += __shfl_xor_sync(0xffffffffu, s, d);
    if (lane == 0) g_cnorm[code] = s;
}

// ---------------------------------------------------------------------------
// Split each code row into bf16 [hi(128) | lo(128) | hi(128) | pad(8)=0]
__global__ void prep_e2_kernel(const float* __restrict__ embed)
{
    const int row = blockIdx.x;       // 0..32767
    const int d   = threadIdx.x;      // 0..127
    float v = embed[(size_t)row * D_ + d];
    __nv_bfloat16 hi = __float2bfloat16(v);
    __nv_bfloat16 lo = __float2bfloat16(v - __bfloat162float(hi));
    g_e2[(size_t)row * EPITCH + d]       = hi;
    g_e2[(size_t)row * EPITCH + 128 + d] = lo;
    g_e2[(size_t)row * EPITCH + 256 + d] = hi;
    if (d < 8) g_e2[(size_t)row * EPITCH + 384 + d] = __float2bfloat16(0.0f);
}

// ---------------------------------------------------------------------------
__device__ __forceinline__ uint32_t smem_u32(const void* p) {
    uint32_t a;
    asm("{ .reg .u64 t; cvta.to.shared.u64 t, %1; cvt.u32.u64 %0, t; }"
        : "=r"(a) : "l"(p));
    return a;
}

__device__ __forceinline__ void ldsm_x4(uint32_t& r0, uint32_t& r1,
                                        uint32_t& r2, uint32_t& r3, uint32_t addr)
{
    asm volatile("ldmatrix.sync.aligned.m8n8.x4.shared.b16 {%0,%1,%2,%3}, [%4];"
                 : "=r"(r0), "=r"(r1), "=r"(r2), "=r"(r3) : "r"(addr));
}

__device__ __forceinline__ void mma16816(float* c, const uint32_t* a,
                                         uint32_t b0, uint32_t b1)
{
    asm volatile(
        "mma.sync.aligned.m16n8k16.row.col.f32.bf16.bf16.f32 "
        "{%0,%1,%2,%3}, {%4,%5,%6,%7}, {%8,%9}, {%0,%1,%2,%3};"
        : "+f"(c[0]), "+f"(c[1]), "+f"(c[2]), "+f"(c[3])
        : "r"(a[0]), "r"(a[1]), "r"(a[2]), "r"(a[3]), "r"(b0), "r"(b1));
}

// ---------------------------------------------------------------------------
// HMMA RVQ layer. 256 threads (8 warps), 128 points/block.
// A' = [r_hi|r_hi|r_lo] (128 x 384 bf16) in smem; codes in 16 chunks of 64.
// Warps tiled 2(M=64) x 4(N=16); k16-steps = 24. D dumped to smem per chunk;
// 2 threads/point track windowed candidates; exact fp32 rescore at the end
// reproduces the R7 f32x2 summation order bit-exactly.
// smem: A 100352 + B 50176 + D 128x66x4=33792 + sidx 512 = 184832 B.
// ---------------------------------------------------------------------------
#define SM_A 0
#define SM_B 100352
#define SM_D 150528
#define SM_SIDX 184320
#define SM_TOTAL 184832
#define DPITCH 66

__global__ void __launch_bounds__(256, 1)
rvq_mma_kernel(const float* __restrict__ embed, int q, float* __restrict__ out)
{
    extern __shared__ char smem[];
    char*  As   = smem + SM_A;
    char*  Bs   = smem + SM_B;
    float* Ds   = (float*)(smem + SM_D);
    int*   sidx = (int*)(smem + SM_SIDX);
    const uint32_t sbase = smem_u32(smem);

    const int tid  = threadIdx.x;
    const int wid  = tid >> 5;
    const int lane = tid & 31;
    const int blockStart = blockIdx.x * 128;

    const int warpM = wid >> 2;          // 0..1 -> rows mBase = warpM*64
    const int warpN = wid & 3;           // 0..3 -> cols nBase = warpN*16
    const int mBase = warpM * 64;
    const int nBase = warpN * 16;

    // ---- build A' = [r_hi | r_hi | r_lo] bf16, padded rows of 392 ----
    for (int u = tid; u < 128 * 48; u += 256) {
        int row = u / 48, g = u % 48;
        int sec = g >> 4;                // 0,1 = hi section, 2 = lo section
        int dbase = (g & 15) * 8;
        int n = blockStart + row;
        if (n >= N_) n = 0;
        const float* rr = g_resid + (size_t)n * D_;
        union { __nv_bfloat16 h[8]; uint4 v; } pk;
        #pragma unroll
        for (int j = 0; j < 8; j++) {
            float v = rr[dbase + j];
            __nv_bfloat16 hi = __float2bfloat16(v);
            pk.h[j] = (sec < 2) ? hi : __float2bfloat16(v - __bfloat162float(hi));
        }
        *(uint4*)(As + row * ROWB + g * 16) = pk.v;
    }
    // zero A pad columns (k = 384..391) so LDSM never reads junk (harmless anyway)
    for (int u = tid; u < 128; u += 256)
        *(uint4*)(As + u * ROWB + 768) = make_uint4(0, 0, 0, 0);

    // per-thread candidate state: thread t covers point p = t>>1, cols half*32..
    const int p    = tid >> 1;
    const int half = tid & 1;
    float mbest = -3.4e38f;
    float cs[NCAND]; int ci[NCAND];
    int   cnum = 0;
    bool  ovf = false;

    const float* gcn = g_cnorm + q * K_;
    const int ksel = (lane >> 4) << 4;       // 0 or 16 bytes (k8 select)
    const int rsel = lane & 15;              // row within 16-row group

    for (int ch = 0; ch < 16; ++ch) {
        // ---- copy B' chunk: 64 code rows x 392 bf16 (padded, 16B ops) ----
        const uint4* src = (const uint4*)(g_e2 + (size_t)(q * K_ + ch * 64) * EPITCH);
        for (int u = tid; u < 64 * 49; u += 256) {
            int row = u / 49, c = u % 49;
            *(uint4*)(Bs + row * ROWB + c * 16) = src[(size_t)row * 49 + c];
        }
        __syncthreads();   // B (and on ch==0, A) visible to all LDSM readers

        // ---- GEMM: 24 k16 steps ----
        float acc[4][2][4];
        #pragma unroll
        for (int mt = 0; mt < 4; mt++)
            #pragma unroll
            for (int nt = 0; nt < 2; nt++)
                #pragma unroll
                for (int r = 0; r < 4; r++) acc[mt][nt][r] = 0.0f;

        #pragma unroll 4
        for (int ks = 0; ks < 24; ++ks) {
            const uint32_t kbyte = ks * 32 + ksel;
            uint32_t a[4][4];
            #pragma unroll
            for (int mt = 0; mt < 4; mt++)
                ldsm_x4(a[mt][0], a[mt][1], a[mt][2], a[mt][3],
                        sbase + SM_A + (mBase + mt * 16 + rsel) * ROWB + kbyte);
            uint32_t b0, b1, b2, b3;
            ldsm_x4(b0, b1, b2, b3,
                    sbase + SM_B + (nBase + rsel) * ROWB + kbyte);
            // b-frag: tile n0-7 = {b0,b2}, tile n8-15 = {b1,b3}
            #pragma unroll
            for (int mt = 0; mt < 4; mt++) {
                mma16816(acc[mt][0], a[mt], b0, b2);
                mma16816(acc[mt][1], a[mt], b1, b3);
            }
        }

        // ---- dump D to smem ----
        #pragma unroll
        for (int mt = 0; mt < 4; mt++) {
            const int m = mBase + mt * 16 + (lane >> 2);
            #pragma unroll
            for (int nt = 0; nt < 2; nt++) {
                const int n = nBase + nt * 8 + (lane & 3) * 2;
                Ds[m * DPITCH + n]           = acc[mt][nt][0];
                Ds[m * DPITCH + n + 1]       = acc[mt][nt][1];
                Ds[(m + 8) * DPITCH + n]     = acc[mt][nt][2];
                Ds[(m + 8) * DPITCH + n + 1] = acc[mt][nt][3];
            }
        }
        __syncthreads();   // D complete before scan; LDSM reads done before next B copy

        // ---- scan: thread covers 32 cols of its point ----
        const float* drow = Ds + p * DPITCH + half * 32;
        #pragma unroll 8
        for (int j = 0; j < 32; j++) {
            const int idx = ch * 64 + half * 32 + j;
            const float s = 2.0f * drow[j] - __ldg(&gcn[idx]);
            if (s > mbest) mbest = s;
            if (s >= mbest - WIN) {
                if (cnum < NCAND) { cs[cnum] = s; ci[cnum] = idx; cnum++; }
                else {
                    int w = 0;
                    #pragma unroll
                    for (int t = 0; t < NCAND; t++)
                        if (cs[t] >= mbest - WIN) { cs[w] = cs[t]; ci[w] = ci[t]; w++; }
                    if (w < NCAND) { cs[w] = s; ci[w] = idx; cnum = w + 1; }
                    else ovf = true;
                }
            }
        }
        // next iteration's B copy races only with other threads' scan reads of Ds
        // (disjoint regions) — safe; the top-of-loop sync orders the B copy.
    }

    // ---- merge the two half-threads + exact rescore ----
    const bool valid = (blockStart + p) < N_;
    const float gm = fmaxf(mbest, __shfl_xor_sync(0xffffffffu, mbest, 1));
    const int oovf = __shfl_xor_sync(0xffffffffu, (int)ovf, 1);
    const bool anyovf = ovf || (oovf != 0);

    const float* rrow = g_resid + (size_t)(blockStart + p) * D_;
    auto score_exact = [&](int idx) -> float {
        const float* e = embed + ((size_t)q * K_ + idx) * D_;
        float aLo = 0.0f, aHi = 0.0f;
        #pragma unroll 4
        for (int d4 = 0; d4 < 32; d4++) {
            aLo = fmaf(rrow[d4 * 4 + 0], __ldg(&e[d4 * 4 + 0]), aLo);
            aHi = fmaf(rrow[d4 * 4 + 1], __ldg(&e[d4 * 4 + 1]), aHi);
            aLo = fmaf(rrow[d4 * 4 + 2], __ldg(&e[d4 * 4 + 2]), aLo);
            aHi = fmaf(rrow[d4 * 4 + 3], __ldg(&e[d4 * 4 + 3]), aHi);
        }
        return 2.0f * (aLo + aHi) - __ldg(&gcn[idx]);
    };

    float bestE = -3.4e38f;
    int   bestI = 0x7fffffff;
    if (valid && !anyovf) {
        for (int t = 0; t < cnum; t++) {
            if (cs[t] < gm - WIN) continue;
            const float s = score_exact(ci[t]);
            if (s > bestE || (s == bestE && ci[t] < bestI)) { bestE = s; bestI = ci[t]; }
        }
    }
    {   // partner exchange (uniform shfl)
        const float oe = __shfl_xor_sync(0xffffffffu, bestE, 1);
        const int   oi = __shfl_xor_sync(0xffffffffu, bestI, 1);
        if (oe > bestE || (oe == bestE && oi < bestI)) { bestE = oe; bestI = oi; }
    }
    if (valid && anyovf && half == 0) {
        bestE = -3.4e38f; bestI = 0;
        for (int idx = 0; idx < K_; idx++) {
            const float s = score_exact(idx);
            if (s > bestE) { bestE = s; bestI = idx; }   // first-max, ascending
        }
    }
    if (half == 0) sidx[p] = (bestI == 0x7fffffff) ? 0 : bestI;
    __syncthreads();

    // ---- write indices as float ----
    if (tid < 128) {
        int n = blockStart + tid;
        if (n < N_) out[(size_t)q * N_ + n] = (float)sidx[tid];
    }

    // ---- residual update: r(global) - e[best] -> g_resid ----
    const float4* eq4 = (const float4*)(embed + (size_t)q * K_ * D_);
    float4* rg4 = (float4*)g_resid;
    #pragma unroll
    for (int i = 0; i < 16; i++) {
        int f = tid + 256 * i;
        int pp = f >> 5, d4 = f & 31;
        int n = blockStart + pp;
        if (n < N_) {
            float4 r = rg4[(size_t)n * 32 + d4];
            float4 e = eq4[(size_t)sidx[pp] * 32 + d4];
            float4 w;
            w.x = r.x - e.x; w.y = r.y - e.y; w.z = r.z - e.z; w.w = r.w - e.w;
            rg4[(size_t)n * 32 + d4] = w;
        }
    }
}

// ---------------------------------------------------------------------------
extern "C" void kernel_launch(void* const* d_in, const int* in_sizes, int n_in,
                              void* d_out, int out_size)
{
    const float* embeddings = (const float*)d_in[0];
    const float* embed      = (const float*)d_in[1];
    if (n_in >= 2 && in_sizes[0] == Q_ * K_ * D_ && in_sizes[1] == B_ * D_ * T_) {
        const float* t = embeddings; embeddings = embed; embed = t;
    }
    float* out = (float*)d_out;

    cudaFuncSetAttribute(rvq_mma_kernel,
                         cudaFuncAttributeMaxDynamicSharedMemorySize, SM_TOTAL);

    transpose_kernel<<<dim3(71, 4, 32), dim3(32, 8)>>>(embeddings);
    cnorm_kernel<<<4096, 256>>>(embed);
    prep_e2_kernel<<<Q_ * K_, 128>>>(embed);
    for (int q = 0; q < Q_; q++) {
        rvq_mma_kernel<<<NBLK, 256, SM_TOTAL>>>(embed, q, out);
    }
}

// round 12
// speedup vs baseline: 1.3031x; 1.3031x over previous
#include <cuda_runtime.h>
#include <cuda_bf16.h>
#include <cstdint>

#define B_ 32
#define D_ 128
#define T_ 2250
#define Q_ 32
#define K_ 1024
#define N_ (B_*T_)          // 72000
#define NBLK 563            // ceil(N/128)
#define WIN 0.02f
#define NC 4                // candidate slots per lane per point

#define EPITCH 392          // bf16 per padded row (784 B)
#define ROWB 784

__device__ __align__(16) float g_resid[(size_t)N_ * D_];
__device__ __align__(16) float g_cnorm[Q_ * K_];
__device__ __align__(16) __nv_bfloat16 g_e2[(size_t)Q_ * K_ * EPITCH];

// ---------------------------------------------------------------------------
__global__ void transpose_kernel(const float* __restrict__ in)
{
    __shared__ float tile[32][33];
    const int b  = blockIdx.z;
    const int t0 = blockIdx.x * 32;
    const int d0 = blockIdx.y * 32;
    const int tx = threadIdx.x;
    const int ty = threadIdx.y;

    #pragma unroll
    for (int k = 0; k < 4; k++) {
        int d = d0 + ty + k * 8;
        int t = t0 + tx;
        float v = 0.0f;
        if (t < T_) v = in[((size_t)b * D_ + d) * T_ + t];
        tile[ty + k * 8][tx] = v;
    }
    __syncthreads();
    #pragma unroll
    for (int k = 0; k < 4; k++) {
        int t = t0 + ty + k * 8;
        int d = d0 + tx;
        if (t < T_) g_resid[((size_t)b * T_ + t) * D_ + d] = tile[tx][ty + k * 8];
    }
}

// ---------------------------------------------------------------------------
__global__ void cnorm_kernel(const float* __restrict__ embed)
{
    const int wid  = threadIdx.x >> 5;
    const int lane = threadIdx.x & 31;
    const int code = blockIdx.x * 8 + wid;
    float s = 0.0f;
    #pragma unroll
    for (int j = 0; j < 4; j++) {
        float v = embed[(size_t)code * D_ + lane + 32 * j];
        s = fmaf(v, v, s);
    }
    #pragma unroll
    for (int d = 16; d; d >>= 1) s += __shfl_xor_sync(0xffffffffu, s, d);
    if (lane == 0) g_cnorm[code] = s;
}

// ---------------------------------------------------------------------------
__global__ void prep_e2_kernel(const float* __restrict__ embed)
{
    const int row = blockIdx.x;
    const int d   = threadIdx.x;
    float v = embed[(size_t)row * D_ + d];
    __nv_bfloat16 hi = __float2bfloat16(v);
    __nv_bfloat16 lo = __float2bfloat16(v - __bfloat162float(hi));
    g_e2[(size_t)row * EPITCH + d]       = hi;
    g_e2[(size_t)row * EPITCH + 128 + d] = lo;
    g_e2[(size_t)row * EPITCH + 256 + d] = hi;
    if (d < 8) g_e2[(size_t)row * EPITCH + 384 + d] = __float2bfloat16(0.0f);
}

// ---------------------------------------------------------------------------
__device__ __forceinline__ uint32_t smem_u32(const void* p) {
    uint32_t a;
    asm("{ .reg .u64 t; cvta.to.shared.u64 t, %1; cvt.u32.u64 %0, t; }"
        : "=r"(a) : "l"(p));
    return a;
}
__device__ __forceinline__ void ldsm_x4(uint32_t& r0, uint32_t& r1,
                                        uint32_t& r2, uint32_t& r3, uint32_t addr)
{
    asm volatile("ldmatrix.sync.aligned.m8n8.x4.shared.b16 {%0,%1,%2,%3}, [%4];"
                 : "=r"(r0), "=r"(r1), "=r"(r2), "=r"(r3) : "r"(addr));
}
__device__ __forceinline__ void mma16816(float* c, const uint32_t* a,
                                         uint32_t b0, uint32_t b1)
{
    asm volatile(
        "mma.sync.aligned.m16n8k16.row.col.f32.bf16.bf16.f32 "
        "{%0,%1,%2,%3}, {%4,%5,%6,%7}, {%8,%9}, {%0,%1,%2,%3};"
        : "+f"(c[0]), "+f"(c[1]), "+f"(c[2]), "+f"(c[3])
        : "r"(a[0]), "r"(a[1]), "r"(a[2]), "r"(a[3]), "r"(b0), "r"(b1));
}
__device__ __forceinline__ void cp_async16(void* smem_dst, const void* gmem_src)
{
    unsigned saddr = (unsigned)__cvta_generic_to_shared(smem_dst);
    asm volatile("cp.async.cg.shared.global [%0], [%1], 16;"
                 :: "r"(saddr), "l"(gmem_src) : "memory");
}
__device__ __forceinline__ void cp_async_commit()
{ asm volatile("cp.async.commit_group;" ::: "memory"); }
__device__ __forceinline__ void cp_async_wait_all()
{ asm volatile("cp.async.wait_group 0;" ::: "memory"); }

// candidate update (windowed, running local max)
#define CAND_UPD(s, idx, mb, cs, ci, cn, ovf) do {                            \
    if ((s) > (mb)) (mb) = (s);                                               \
    if ((s) >= (mb) - WIN) {                                                  \
        if ((cn) < NC) { (cs)[(cn)] = (s); (ci)[(cn)] = (idx); (cn)++; }      \
        else {                                                                \
            int _w = 0;                                                       \
            _Pragma("unroll")                                                 \
            for (int _t = 0; _t < NC; _t++)                                   \
                if ((cs)[_t] >= (mb) - WIN) {                                 \
                    (cs)[_w] = (cs)[_t]; (ci)[_w] = (ci)[_t]; _w++; }         \
            if (_w < NC) { (cs)[_w] = (s); (ci)[_w] = (idx); (cn) = _w + 1; } \
            else (ovf) = 1;                                                   \
        }                                                                     \
    }                                                                         \
} while (0)

// ---------------------------------------------------------------------------
// HMMA RVQ layer, register-resident A.
// 256 threads = 8 warps; warp w owns M-rows [w*16, w*16+16), all N=64 of the
// current chunk. A' = [r_hi|r_hi|r_lo] (K=384) fragments live in registers
// (24 k16-steps x 4 regs). B chunks (64 codes) cp.async double-buffered in
// the smem region first used for A staging. Scores scanned directly from MMA
// accumulator fragments; windowed candidates + exact fp32 rescore (R7's f32x2
// summation order, bit-exact) + first-max tie-break.
// smem: 2x50176 B buffers (= 100352 A staging) + cnorm 4096 + sidx 512.
// ---------------------------------------------------------------------------
#define SM_BUF0 0
#define SM_BUF1 50176
#define SM_CN   100352
#define SM_SIDX 104448
#define SM_TOTAL 104960

__global__ void __launch_bounds__(256, 1)
rvq_mma_kernel(const float* __restrict__ embed, int q, float* __restrict__ out)
{
    extern __shared__ char smem[];
    float* gcn  = (float*)(smem + SM_CN);
    int*   sidx = (int*)(smem + SM_SIDX);
    const uint32_t sbase = smem_u32(smem);

    const int tid  = threadIdx.x;
    const int wid  = tid >> 5;
    const int lane = tid & 31;
    const int blockStart = blockIdx.x * 128;

    // ---- cnorm chunk -> smem ----
    for (int u = tid; u < K_; u += 256) gcn[u] = g_cnorm[q * K_ + u];

    // ---- build A' staging = [r_hi | r_hi | r_lo] (128 x 384 bf16) ----
    for (int u = tid; u < 128 * 48; u += 256) {
        int row = u / 48, g = u % 48;
        int sec = g >> 4;
        int dbase = (g & 15) * 8;
        int n = blockStart + row;
        if (n >= N_) n = 0;
        const float* rr = g_resid + (size_t)n * D_;
        union { __nv_bfloat16 h[8]; uint4 v; } pk;
        #pragma unroll
        for (int j = 0; j < 8; j++) {
            float v = rr[dbase + j];
            __nv_bfloat16 hi = __float2bfloat16(v);
            pk.h[j] = (sec < 2) ? hi : __float2bfloat16(v - __bfloat162float(hi));
        }
        *(uint4*)(smem + row * ROWB + g * 16) = pk.v;
    }
    __syncthreads();

    // ---- A fragments -> registers (96 regs/thread) ----
    const int rsel = lane & 15;
    const int ksel = (lane >> 4) << 4;
    uint32_t a[24][4];
    {
        const uint32_t ab = sbase + (wid * 16 + rsel) * ROWB + ksel;
        #pragma unroll
        for (int ks = 0; ks < 24; ks++)
            ldsm_x4(a[ks][0], a[ks][1], a[ks][2], a[ks][3], ab + ks * 32);
    }
    __syncthreads();   // staging dead -> reuse as B double buffer

    // ---- prefetch B chunk 0 ----
    {
        const uint4* src = (const uint4*)(g_e2 + (size_t)(q * K_) * EPITCH);
        for (int u = tid; u < 64 * 49; u += 256) {
            int row = u / 49, c = u % 49;
            cp_async16(smem + SM_BUF0 + row * ROWB + c * 16, src + (size_t)row * 49 + c);
        }
        cp_async_commit();
    }

    // ---- candidate state: 2 points per lane (rows r, r+8 of warp slice) ----
    float mb0 = -3.4e38f, mb1 = -3.4e38f;
    float cs0[NC], cs1[NC];
    int   ci0[NC], ci1[NC];
    int   cn0 = 0, cn1 = 0, ovf0 = 0, ovf1 = 0;

    for (int ch = 0; ch < 16; ++ch) {
        cp_async_wait_all();
        __syncthreads();   // buffer ch&1 ready; prior readers done with it

        if (ch < 15) {
            const uint4* src = (const uint4*)(g_e2 + (size_t)(q * K_ + (ch + 1) * 64) * EPITCH);
            char* dst = smem + (((ch + 1) & 1) ? SM_BUF1 : SM_BUF0);
            for (int u = tid; u < 64 * 49; u += 256) {
                int row = u / 49, c = u % 49;
                cp_async16(dst + row * ROWB + c * 16, src + (size_t)row * 49 + c);
            }
        }
        cp_async_commit();

        const uint32_t bb = sbase + ((ch & 1) ? SM_BUF1 : SM_BUF0)
                          + rsel * ROWB + ksel;

        float acc[8][4];
        #pragma unroll
        for (int i = 0; i < 8; i++)
            acc[i][0] = acc[i][1] = acc[i][2] = acc[i][3] = 0.0f;

        #pragma unroll
        for (int ks = 0; ks < 24; ++ks) {
            uint32_t b[4][4];
            #pragma unroll
            for (int n16 = 0; n16 < 4; n16++)
                ldsm_x4(b[n16][0], b[n16][1], b[n16][2], b[n16][3],
                        bb + n16 * (16 * ROWB) + ks * 32);
            #pragma unroll
            for (int n16 = 0; n16 < 4; n16++) {
                mma16816(acc[2 * n16],     a[ks], b[n16][0], b[n16][2]);
                mma16816(acc[2 * n16 + 1], a[ks], b[n16][1], b[n16][3]);
            }
        }

        // ---- in-register scan ----
        #pragma unroll
        for (int n8 = 0; n8 < 8; n8++) {
            const int ncol = n8 * 8 + (lane & 3) * 2;
            #pragma unroll
            for (int e = 0; e < 2; e++) {
                const int idx = ch * 64 + ncol + e;
                const float cnv = gcn[idx];
                {
                    const float s = 2.0f * acc[n8][e] - cnv;
                    CAND_UPD(s, idx, mb0, cs0, ci0, cn0, ovf0);
                }
                {
                    const float s = 2.0f * acc[n8][2 + e] - cnv;
                    CAND_UPD(s, idx, mb1, cs1, ci1, cn1, ovf1);
                }
            }
        }
    }
    cp_async_wait_all();   // drain trailing empty group

    // ---- per-point merge + exact rescore ----
    const int prow0 = wid * 16 + (lane >> 2);
    const int prow1 = prow0 + 8;
    float gm0 = mb0, gm1 = mb1;
    #pragma unroll
    for (int d = 1; d < 4; d <<= 1) {
        gm0 = fmaxf(gm0, __shfl_xor_sync(0xffffffffu, gm0, d));
        gm1 = fmaxf(gm1, __shfl_xor_sync(0xffffffffu, gm1, d));
        ovf0 |= __shfl_xor_sync(0xffffffffu, ovf0, d);
        ovf1 |= __shfl_xor_sync(0xffffffffu, ovf1, d);
    }

    int n0 = blockStart + prow0; if (n0 >= N_) n0 = 0;
    int n1 = blockStart + prow1; if (n1 >= N_) n1 = 0;

    auto score_exact = [&](int nn, int idx) -> float {
        const float* rr = g_resid + (size_t)nn * D_;
        const float* e  = embed + ((size_t)q * K_ + idx) * D_;
        float aLo = 0.0f, aHi = 0.0f;
        #pragma unroll 4
        for (int d4 = 0; d4 < 32; d4++) {
            aLo = fmaf(rr[d4 * 4 + 0], __ldg(&e[d4 * 4 + 0]), aLo);
            aHi = fmaf(rr[d4 * 4 + 1], __ldg(&e[d4 * 4 + 1]), aHi);
            aLo = fmaf(rr[d4 * 4 + 2], __ldg(&e[d4 * 4 + 2]), aLo);
            aHi = fmaf(rr[d4 * 4 + 3], __ldg(&e[d4 * 4 + 3]), aHi);
        }
        return 2.0f * (aLo + aHi) - gcn[idx];
    };

    float bE0 = -3.4e38f, bE1 = -3.4e38f;
    int   bI0 = 0x7fffffff, bI1 = 0x7fffffff;
    for (int t = 0; t < cn0; t++) {
        if (cs0[t] < gm0 - WIN) continue;
        const float s = score_exact(n0, ci0[t]);
        if (s > bE0 || (s == bE0 && ci0[t] < bI0)) { bE0 = s; bI0 = ci0[t]; }
    }
    for (int t = 0; t < cn1; t++) {
        if (cs1[t] < gm1 - WIN) continue;
        const float s = score_exact(n1, ci1[t]);
        if (s > bE1 || (s == bE1 && ci1[t] < bI1)) { bE1 = s; bI1 = ci1[t]; }
    }
    #pragma unroll
    for (int d = 1; d < 4; d <<= 1) {
        const float oe0 = __shfl_xor_sync(0xffffffffu, bE0, d);
        const int   oi0 = __shfl_xor_sync(0xffffffffu, bI0, d);
        if (oe0 > bE0 || (oe0 == bE0 && oi0 < bI0)) { bE0 = oe0; bI0 = oi0; }
        const float oe1 = __shfl_xor_sync(0xffffffffu, bE1, d);
        const int   oi1 = __shfl_xor_sync(0xffffffffu, bI1, d);
        if (oe1 > bE1 || (oe1 == bE1 && oi1 < bI1)) { bE1 = oe1; bI1 = oi1; }
    }
    if ((lane & 3) == 0) {
        if (ovf0) {
            bE0 = -3.4e38f; bI0 = 0;
            for (int idx = 0; idx < K_; idx++) {
                const float s = score_exact(n0, idx);
                if (s > bE0) { bE0 = s; bI0 = idx; }
            }
        }
        if (ovf1) {
            bE1 = -3.4e38f; bI1 = 0;
            for (int idx = 0; idx < K_; idx++) {
                const float s = score_exact(n1, idx);
                if (s > bE1) { bE1 = s; bI1 = idx; }
            }
        }
        sidx[prow0] = (bI0 == 0x7fffffff) ? 0 : bI0;
        sidx[prow1] = (bI1 == 0x7fffffff) ? 0 : bI1;
    }
    __syncthreads();

    // ---- write indices as float ----
    if (tid < 128) {
        int n = blockStart + tid;
        if (n < N_) out[(size_t)q * N_ + n] = (float)sidx[tid];
    }

    // ---- residual update: r - e[best] -> g_resid ----
    const float4* eq4 = (const float4*)(embed + (size_t)q * K_ * D_);
    float4* rg4 = (float4*)g_resid;
    #pragma unroll
    for (int i = 0; i < 16; i++) {
        int f = tid + 256 * i;
        int pp = f >> 5, d4 = f & 31;
        int n = blockStart + pp;
        if (n < N_) {
            float4 r = rg4[(size_t)n * 32 + d4];
            float4 e = eq4[(size_t)sidx[pp] * 32 + d4];
            float4 w;
            w.x = r.x - e.x; w.y = r.y - e.y; w.z = r.z - e.z; w.w = r.w - e.w;
            rg4[(size_t)n * 32 + d4] = w;
        }
    }
}

// ---------------------------------------------------------------------------
extern "C" void kernel_launch(void* const* d_in, const int* in_sizes, int n_in,
                              void* d_out, int out_size)
{
    const float* embeddings = (const float*)d_in[0];
    const float* embed      = (const float*)d_in[1];
    if (n_in >= 2 && in_sizes[0] == Q_ * K_ * D_ && in_sizes[1] == B_ * D_ * T_) {
        const float* t = embeddings; embeddings = embed; embed = t;
    }
    float* out = (float*)d_out;

    cudaFuncSetAttribute(rvq_mma_kernel,
                         cudaFuncAttributeMaxDynamicSharedMemorySize, SM_TOTAL);

    transpose_kernel<<<dim3(71, 4, 32), dim3(32, 8)>>>(embeddings);
    cnorm_kernel<<<4096, 256>>>(embed);
    prep_e2_kernel<<<Q_ * K_, 128>>>(embed);
    for (int q = 0; q < Q_; q++) {
        rvq_mma_kernel<<<NBLK, 256, SM_TOTAL>>>(embed, q, out);
    }
}

// round 13
// speedup vs baseline: 1.3036x; 1.0004x over previous
#include <cuda_runtime.h>
#include <cuda_bf16.h>
#include <cstdint>

#define B_ 32
#define D_ 128
#define T_ 2250
#define Q_ 32
#define K_ 1024
#define N_ (B_*T_)          // 72000
#define NBLK 563            // ceil(N/128)
#define WIN 0.02f
#define NC 4                // candidate slots per lane per point

#define EPITCH 392          // bf16 per padded row (784 B)
#define ROWB 784

__device__ __align__(16) float g_resid[(size_t)N_ * D_];
__device__ __align__(16) float g_cnorm[Q_ * K_];
__device__ __align__(16) __nv_bfloat16 g_e2[(size_t)Q_ * K_ * EPITCH];

// ---------------------------------------------------------------------------
__global__ void transpose_kernel(const float* __restrict__ in)
{
    __shared__ float tile[32][33];
    const int b  = blockIdx.z;
    const int t0 = blockIdx.x * 32;
    const int d0 = blockIdx.y * 32;
    const int tx = threadIdx.x;
    const int ty = threadIdx.y;

    #pragma unroll
    for (int k = 0; k < 4; k++) {
        int d = d0 + ty + k * 8;
        int t = t0 + tx;
        float v = 0.0f;
        if (t < T_) v = in[((size_t)b * D_ + d) * T_ + t];
        tile[ty + k * 8][tx] = v;
    }
    __syncthreads();
    #pragma unroll
    for (int k = 0; k < 4; k++) {
        int t = t0 + ty + k * 8;
        int d = d0 + tx;
        if (t < T_) g_resid[((size_t)b * T_ + t) * D_ + d] = tile[tx][ty + k * 8];
    }
}

// ---------------------------------------------------------------------------
__global__ void cnorm_kernel(const float* __restrict__ embed)
{
    const int wid  = threadIdx.x >> 5;
    const int lane = threadIdx.x & 31;
    const int code = blockIdx.x * 8 + wid;
    float s = 0.0f;
    #pragma unroll
    for (int j = 0; j < 4; j++) {
        float v = embed[(size_t)code * D_ + lane + 32 * j];
        s = fmaf(v, v, s);
    }
    #pragma unroll
    for (int d = 16; d; d >>= 1) s += __shfl_xor_sync(0xffffffffu, s, d);
    if (lane == 0) g_cnorm[code] = s;
}

// ---------------------------------------------------------------------------
__global__ void prep_e2_kernel(const float* __restrict__ embed)
{
    const int row = blockIdx.x;
    const int d   = threadIdx.x;
    float v = embed[(size_t)row * D_ + d];
    __nv_bfloat16 hi = __float2bfloat16(v);
    __nv_bfloat16 lo = __float2bfloat16(v - __bfloat162float(hi));
    g_e2[(size_t)row * EPITCH + d]       = hi;
    g_e2[(size_t)row * EPITCH + 128 + d] = lo;
    g_e2[(size_t)row * EPITCH + 256 + d] = hi;
    if (d < 8) g_e2[(size_t)row * EPITCH + 384 + d] = __float2bfloat16(0.0f);
}

// ---------------------------------------------------------------------------
__device__ __forceinline__ uint32_t smem_u32(const void* p) {
    uint32_t a;
    asm("{ .reg .u64 t; cvta.to.shared.u64 t, %1; cvt.u32.u64 %0, t; }"
        : "=r"(a) : "l"(p));
    return a;
}
__device__ __forceinline__ void ldsm_x4(uint32_t& r0, uint32_t& r1,
                                        uint32_t& r2, uint32_t& r3, uint32_t addr)
{
    asm volatile("ldmatrix.sync.aligned.m8n8.x4.shared.b16 {%0,%1,%2,%3}, [%4];"
                 : "=r"(r0), "=r"(r1), "=r"(r2), "=r"(r3) : "r"(addr));
}
__device__ __forceinline__ void mma16816(float* c, const uint32_t* a,
                                         uint32_t b0, uint32_t b1)
{
    asm volatile(
        "mma.sync.aligned.m16n8k16.row.col.f32.bf16.bf16.f32 "
        "{%0,%1,%2,%3}, {%4,%5,%6,%7}, {%8,%9}, {%0,%1,%2,%3};"
        : "+f"(c[0]), "+f"(c[1]), "+f"(c[2]), "+f"(c[3])
        : "r"(a[0]), "r"(a[1]), "r"(a[2]), "r"(a[3]), "r"(b0), "r"(b1));
}
__device__ __forceinline__ void cp_async16(void* smem_dst, const void* gmem_src)
{
    unsigned saddr = (unsigned)__cvta_generic_to_shared(smem_dst);
    asm volatile("cp.async.cg.shared.global [%0], [%1], 16;"
                 :: "r"(saddr), "l"(gmem_src) : "memory");
}
__device__ __forceinline__ void cp_async_commit()
{ asm volatile("cp.async.commit_group;" ::: "memory"); }
__device__ __forceinline__ void cp_async_wait_all()
{ asm volatile("cp.async.wait_group 0;" ::: "memory"); }

#define CAND_UPD(s, idx, mb, cs, ci, cn, ovf) do {                            \
    if ((s) > (mb)) (mb) = (s);                                               \
    if ((s) >= (mb) - WIN) {                                                  \
        if ((cn) < NC) { (cs)[(cn)] = (s); (ci)[(cn)] = (idx); (cn)++; }      \
        else {                                                                \
            int _w = 0;                                                       \
            _Pragma("unroll")                                                 \
            for (int _t = 0; _t < NC; _t++)                                   \
                if ((cs)[_t] >= (mb) - WIN) {                                 \
                    (cs)[_w] = (cs)[_t]; (ci)[_w] = (ci)[_t]; _w++; }         \
            if (_w < NC) { (cs)[_w] = (s); (ci)[_w] = (idx); (cn) = _w + 1; } \
            else (ovf) = 1;                                                   \
        }                                                                     \
    }                                                                         \
} while (0)

// ---------------------------------------------------------------------------
// HMMA RVQ layer, register-resident A + software-pipelined B fragments.
// 256 threads = 8 warps; warp w owns M-rows [w*16, w*16+16), all N=64.
// b[2][4][4] register double-buffer: LDSM for k-step ks+1 issues interleaved
// with k-step ks's MMAs, hiding the 29-cyc smem latency behind the MMA burst.
// Candidate window + exact fp32 rescore (R7 f32x2 order) unchanged.
// ---------------------------------------------------------------------------
#define SM_BUF0 0
#define SM_BUF1 50176
#define SM_CN   100352
#define SM_SIDX 104448
#define SM_TOTAL 104960

__global__ void __launch_bounds__(256, 1)
rvq_mma_kernel(const float* __restrict__ embed, int q, float* __restrict__ out)
{
    extern __shared__ char smem[];
    float* gcn  = (float*)(smem + SM_CN);
    int*   sidx = (int*)(smem + SM_SIDX);
    const uint32_t sbase = smem_u32(smem);

    const int tid  = threadIdx.x;
    const int wid  = tid >> 5;
    const int lane = tid & 31;
    const int blockStart = blockIdx.x * 128;

    // ---- cnorm -> smem ----
    for (int u = tid; u < K_; u += 256) gcn[u] = g_cnorm[q * K_ + u];

    // ---- build A' staging = [r_hi | r_hi | r_lo] (128 x 384 bf16) ----
    for (int u = tid; u < 128 * 48; u += 256) {
        int row = u / 48, g = u % 48;
        int sec = g >> 4;
        int dbase = (g & 15) * 8;
        int n = blockStart + row;
        if (n >= N_) n = 0;
        const float* rr = g_resid + (size_t)n * D_;
        union { __nv_bfloat16 h[8]; uint4 v; } pk;
        #pragma unroll
        for (int j = 0; j < 8; j++) {
            float v = rr[dbase + j];
            __nv_bfloat16 hi = __float2bfloat16(v);
            pk.h[j] = (sec < 2) ? hi : __float2bfloat16(v - __bfloat162float(hi));
        }
        *(uint4*)(smem + row * ROWB + g * 16) = pk.v;
    }
    __syncthreads();

    // ---- A fragments -> registers ----
    const int rsel = lane & 15;
    const int ksel = (lane >> 4) << 4;
    uint32_t a[24][4];
    {
        const uint32_t ab = sbase + (wid * 16 + rsel) * ROWB + ksel;
        #pragma unroll
        for (int ks = 0; ks < 24; ks++)
            ldsm_x4(a[ks][0], a[ks][1], a[ks][2], a[ks][3], ab + ks * 32);
    }
    __syncthreads();   // staging dead -> reuse as B double buffer

    // ---- prefetch B chunk 0 ----
    {
        const uint4* src = (const uint4*)(g_e2 + (size_t)(q * K_) * EPITCH);
        for (int u = tid; u < 64 * 49; u += 256) {
            int row = u / 49, c = u % 49;
            cp_async16(smem + SM_BUF0 + row * ROWB + c * 16, src + (size_t)row * 49 + c);
        }
        cp_async_commit();
    }

    float mb0 = -3.4e38f, mb1 = -3.4e38f;
    float cs0[NC], cs1[NC];
    int   ci0[NC], ci1[NC];
    int   cn0 = 0, cn1 = 0, ovf0 = 0, ovf1 = 0;

    const uint32_t bsel = rsel * ROWB + ksel;

    for (int ch = 0; ch < 16; ++ch) {
        cp_async_wait_all();
        __syncthreads();   // buffer ch&1 ready; prior readers done with it

        if (ch < 15) {
            const uint4* src = (const uint4*)(g_e2 + (size_t)(q * K_ + (ch + 1) * 64) * EPITCH);
            char* dst = smem + (((ch + 1) & 1) ? SM_BUF1 : SM_BUF0);
            for (int u = tid; u < 64 * 49; u += 256) {
                int row = u / 49, c = u % 49;
                cp_async16(dst + row * ROWB + c * 16, src + (size_t)row * 49 + c);
            }
        }
        cp_async_commit();

        const uint32_t bb = sbase + ((ch & 1) ? SM_BUF1 : SM_BUF0) + bsel;

        float acc[8][4];
        #pragma unroll
        for (int i = 0; i < 8; i++)
            acc[i][0] = acc[i][1] = acc[i][2] = acc[i][3] = 0.0f;

        // ---- software-pipelined GEMM: 24 k16 steps ----
        uint32_t b[2][4][4];
        #pragma unroll
        for (int n16 = 0; n16 < 4; n16++)
            ldsm_x4(b[0][n16][0], b[0][n16][1], b[0][n16][2], b[0][n16][3],
                    bb + n16 * (16 * ROWB));

        #pragma unroll
        for (int ks = 0; ks < 24; ++ks) {
            const int cur = ks & 1, nxt = cur ^ 1;
            #pragma unroll
            for (int n16 = 0; n16 < 4; n16++) {
                if (ks < 23)
                    ldsm_x4(b[nxt][n16][0], b[nxt][n16][1],
                            b[nxt][n16][2], b[nxt][n16][3],
                            bb + n16 * (16 * ROWB) + (ks + 1) * 32);
                mma16816(acc[2 * n16],     a[ks], b[cur][n16][0], b[cur][n16][2]);
                mma16816(acc[2 * n16 + 1], a[ks], b[cur][n16][1], b[cur][n16][3]);
            }
        }

        // ---- in-register scan ----
        #pragma unroll
        for (int n8 = 0; n8 < 8; n8++) {
            const int ncol = n8 * 8 + (lane & 3) * 2;
            #pragma unroll
            for (int e = 0; e < 2; e++) {
                const int idx = ch * 64 + ncol + e;
                const float cnv = gcn[idx];
                {
                    const float s = 2.0f * acc[n8][e] - cnv;
                    CAND_UPD(s, idx, mb0, cs0, ci0, cn0, ovf0);
                }
                {
                    const float s = 2.0f * acc[n8][2 + e] - cnv;
                    CAND_UPD(s, idx, mb1, cs1, ci1, cn1, ovf1);
                }
            }
        }
    }
    cp_async_wait_all();

    // ---- per-point merge + exact rescore ----
    const int prow0 = wid * 16 + (lane >> 2);
    const int prow1 = prow0 + 8;
    float gm0 = mb0, gm1 = mb1;
    #pragma unroll
    for (int d = 1; d < 4; d <<= 1) {
        gm0 = fmaxf(gm0, __shfl_xor_sync(0xffffffffu, gm0, d));
        gm1 = fmaxf(gm1, __shfl_xor_sync(0xffffffffu, gm1, d));
        ovf0 |= __shfl_xor_sync(0xffffffffu, ovf0, d);
        ovf1 |= __shfl_xor_sync(0xffffffffu, ovf1, d);
    }

    int n0 = blockStart + prow0; if (n0 >= N_) n0 = 0;
    int n1 = blockStart + prow1; if (n1 >= N_) n1 = 0;

    auto score_exact = [&](int nn, int idx) -> float {
        const float* rr = g_resid + (size_t)nn * D_;
        const float* e  = embed + ((size_t)q * K_ + idx) * D_;
        float aLo = 0.0f, aHi = 0.0f;
        #pragma unroll 4
        for (int d4 = 0; d4 < 32; d4++) {
            aLo = fmaf(rr[d4 * 4 + 0], __ldg(&e[d4 * 4 + 0]), aLo);
            aHi = fmaf(rr[d4 * 4 + 1], __ldg(&e[d4 * 4 + 1]), aHi);
            aLo = fmaf(rr[d4 * 4 + 2], __ldg(&e[d4 * 4 + 2]), aLo);
            aHi = fmaf(rr[d4 * 4 + 3], __ldg(&e[d4 * 4 + 3]), aHi);
        }
        return 2.0f * (aLo + aHi) - gcn[idx];
    };

    float bE0 = -3.4e38f, bE1 = -3.4e38f;
    int   bI0 = 0x7fffffff, bI1 = 0x7fffffff;
    for (int t = 0; t < cn0; t++) {
        if (cs0[t] < gm0 - WIN) continue;
        const float s = score_exact(n0, ci0[t]);
        if (s > bE0 || (s == bE0 && ci0[t] < bI0)) { bE0 = s; bI0 = ci0[t]; }
    }
    for (int t = 0; t < cn1; t++) {
        if (cs1[t] < gm1 - WIN) continue;
        const float s = score_exact(n1, ci1[t]);
        if (s > bE1 || (s == bE1 && ci1[t] < bI1)) { bE1 = s; bI1 = ci1[t]; }
    }
    #pragma unroll
    for (int d = 1; d < 4; d <<= 1) {
        const float oe0 = __shfl_xor_sync(0xffffffffu, bE0, d);
        const int   oi0 = __shfl_xor_sync(0xffffffffu, bI0, d);
        if (oe0 > bE0 || (oe0 == bE0 && oi0 < bI0)) { bE0 = oe0; bI0 = oi0; }
        const float oe1 = __shfl_xor_sync(0xffffffffu, bE1, d);
        const int   oi1 = __shfl_xor_sync(0xffffffffu, bI1, d);
        if (oe1 > bE1 || (oe1 == bE1 && oi1 < bI1)) { bE1 = oe1; bI1 = oi1; }
    }
    if ((lane & 3) == 0) {
        if (ovf0) {
            bE0 = -3.4e38f; bI0 = 0;
            for (int idx = 0; idx < K_; idx++) {
                const float s = score_exact(n0, idx);
                if (s > bE0) { bE0 = s; bI0 = idx; }
            }
        }
        if (ovf1) {
            bE1 = -3.4e38f; bI1 = 0;
            for (int idx = 0; idx < K_; idx++) {
                const float s = score_exact(n1, idx);
                if (s > bE1) { bE1 = s; bI1 = idx; }
            }
        }
        sidx[prow0] = (bI0 == 0x7fffffff) ? 0 : bI0;
        sidx[prow1] = (bI1 == 0x7fffffff) ? 0 : bI1;
    }
    __syncthreads();

    // ---- write indices as float ----
    if (tid < 128) {
        int n = blockStart + tid;
        if (n < N_) out[(size_t)q * N_ + n] = (float)sidx[tid];
    }

    // ---- residual update: r - e[best] -> g_resid ----
    const float4* eq4 = (const float4*)(embed + (size_t)q * K_ * D_);
    float4* rg4 = (float4*)g_resid;
    #pragma unroll
    for (int i = 0; i < 16; i++) {
        int f = tid + 256 * i;
        int pp = f >> 5, d4 = f & 31;
        int n = blockStart + pp;
        if (n < N_) {
            float4 r = rg4[(size_t)n * 32 + d4];
            float4 e = eq4[(size_t)sidx[pp] * 32 + d4];
            float4 w;
            w.x = r.x - e.x; w.y = r.y - e.y; w.z = r.z - e.z; w.w = r.w - e.w;
            rg4[(size_t)n * 32 + d4] = w;
        }
    }
}

// ---------------------------------------------------------------------------
extern "C" void kernel_launch(void* const* d_in, const int* in_sizes, int n_in,
                              void* d_out, int out_size)
{
    const float* embeddings = (const float*)d_in[0];
    const float* embed      = (const float*)d_in[1];
    if (n_in >= 2 && in_sizes[0] == Q_ * K_ * D_ && in_sizes[1] == B_ * D_ * T_) {
        const float* t = embeddings; embeddings = embed; embed = t;
    }
    float* out = (float*)d_out;

    cudaFuncSetAttribute(rvq_mma_kernel,
                         cudaFuncAttributeMaxDynamicSharedMemorySize, SM_TOTAL);

    transpose_kernel<<<dim3(71, 4, 32), dim3(32, 8)>>>(embeddings);
    cnorm_kernel<<<4096, 256>>>(embed);
    prep_e2_kernel<<<Q_ * K_, 128>>>(embed);
    for (int q = 0; q < Q_; q++) {
        rvq_mma_kernel<<<NBLK, 256, SM_TOTAL>>>(embed, q, out);
    }
}